// round 14
// baseline (speedup 1.0000x reference)
#include <cuda_runtime.h>
#include <cuda_bf16.h>
#include <cstdint>
#include <math.h>

#define NF 512
#define NFIELD 30
#define KDIM 40
#define MT 64           // rows per CTA
#define NTHREADS 512

// ---- smem layout (bytes) ----
#define SM_X      0
#define SM_X_BYTES (MT * NF * 2)            // 65536
#define SM_ACC    (SM_X + SM_X_BYTES)
#define SM_TOT    (SM_ACC + MT * 4)         // 65792

// G in mma-fragment order:
//   element (n, k):  u=k>>6, g=n>>6, ks=(k>>4)&3, p=(n>>4)&3, h=(n>>3)&1,
//                    kk=k&15, l=((n&7)<<2)|((kk&7)>>1), w=kk>>3, q=h*2+w
//   byte = ((u*8+g)<<13) + ((ks*4+p)<<9) + (l<<4) + (q<<2) + ((kk&1)<<1)
__device__ __align__(128) unsigned char g_Gt[NF * NF * 2];

// ---------------- helpers ----------------
__device__ __forceinline__ uint32_t smem_u32(const void* p) {
    uint32_t a;
    asm("{ .reg .u64 t; cvta.to.shared.u64 t, %1; cvt.u32.u64 %0, t; }" : "=r"(a) : "l"(p));
    return a;
}
__device__ __forceinline__ uint32_t sw128(uint32_t b) { return b ^ ((b >> 3) & 0x70); }
// X tile: blocked atoms (8 rows x 64 bf16 = 1024B); 8 atoms per 64-col group
__device__ __forceinline__ uint32_t aByte(int r, int k) {
    return (uint32_t)((((r >> 3) + (k >> 6) * 8) << 10) + ((r & 7) << 7) + ((k & 63) << 1));
}
__device__ __forceinline__ void ldsm4(uint32_t* r, uint32_t addr) {
    asm volatile("ldmatrix.sync.aligned.m8n8.x4.shared.b16 {%0,%1,%2,%3}, [%4];"
                 : "=r"(r[0]), "=r"(r[1]), "=r"(r[2]), "=r"(r[3]) : "r"(addr));
}
__device__ __forceinline__ void mma16816(float* c, const uint32_t* a, uint32_t b0, uint32_t b1) {
    asm volatile(
        "mma.sync.aligned.m16n8k16.row.col.f32.bf16.bf16.f32 "
        "{%0,%1,%2,%3}, {%4,%5,%6,%7}, {%8,%9}, {%0,%1,%2,%3};"
        : "+f"(c[0]), "+f"(c[1]), "+f"(c[2]), "+f"(c[3])
        : "r"(a[0]), "r"(a[1]), "r"(a[2]), "r"(a[3]), "r"(b0), "r"(b1));
}

// ---------------------------------------------------------------------------
// Kernel 1: G symmetric; write BOTH mirrors directly into fragment order.
// ---------------------------------------------------------------------------
__device__ __forceinline__ void storeGt(int n, int k, __nv_bfloat16 h) {
    int u = k >> 6, g = n >> 6, ks = (k >> 4) & 3, p = (n >> 4) & 3;
    int hh = (n >> 3) & 1, kk = k & 15;
    int l = ((n & 7) << 2) | ((kk & 7) >> 1);
    int q = hh * 2 + (kk >> 3);
    uint32_t byte = ((uint32_t)((u << 3) | g) << 13) + ((uint32_t)((ks << 2) | p) << 9)
                  + ((uint32_t)l << 4) + ((uint32_t)q << 2) + ((uint32_t)(kk & 1) << 1);
    *reinterpret_cast<__nv_bfloat16*>(g_Gt + byte) = h;
}

__global__ void build_G_kernel(const float* __restrict__ v, const int* __restrict__ f2f) {
    int j = blockIdx.x;
    int i = threadIdx.x;
    if (i < j) return;
    int fj = __ldg(&f2f[j]);
    int fi = __ldg(&f2f[i]);
    const float4* a  = reinterpret_cast<const float4*>(v + ((size_t)i * NFIELD + fj) * KDIM);
    const float4* bp = reinterpret_cast<const float4*>(v + ((size_t)j * NFIELD + fi) * KDIM);
    float s = 0.f;
#pragma unroll
    for (int t = 0; t < KDIM / 4; t++) {
        float4 av = a[t], bv = bp[t];
        s = fmaf(av.x, bv.x, s);
        s = fmaf(av.y, bv.y, s);
        s = fmaf(av.z, bv.z, s);
        s = fmaf(av.w, bv.w, s);
    }
    s *= 0.5f;
    if (i == j) s = 0.f;
    __nv_bfloat16 h = __float2bfloat16(s);
    storeGt(j, i, h);   // B[n=j][k=i]
    storeGt(i, j, h);   // B[n=i][k=j]
}

// ---------------------------------------------------------------------------
// Kernel 2: HMMA quadratic form, barrier-free mainloop, 2 CTAs/SM.
//   MT=64, 16 warps: wm = wid&1 (2 x 32 rows), wn = wid>>1 (8 x 64 cols)
//   -> ONE n-sweep covers all 512 columns. B frags via LDG.128 from
//   fragment-ordered g_Gt (L2/L1-resident, shared across both resident
//   CTAs); A via ldsm from the X smem tile.
// ---------------------------------------------------------------------------
__global__ __launch_bounds__(NTHREADS, 2)
void ffm_hmma_kernel(const float* __restrict__ X, const float* __restrict__ w1g,
                     const float* __restrict__ bg, float* __restrict__ out) {
    extern __shared__ __align__(1024) char smem[];
    const int tid  = threadIdx.x;
    const int lane = tid & 31;
    const int wid  = tid >> 5;
    const int wm   = wid & 1;    // 2 x 32 rows
    const int wn   = wid >> 1;   // 8 x 64 cols  (g = wn)

    uint32_t sb = smem_u32(smem);
    float* accs = reinterpret_cast<float*>(smem + SM_ACC);
    if (tid < MT) accs[tid] = 0.f;

    // ---- X prologue: 64 x 512 f32 -> bf16, swizzled blocked atoms ----
    const float4* Xg = reinterpret_cast<const float4*>(X + (size_t)blockIdx.x * MT * NF);
#pragma unroll 4
    for (int it = 0; it < 16; it++) {
        int f = tid + it * NTHREADS;
        int r = f >> 7;             // 128 float4 per row
        int k = (f & 127) * 4;
        float4 x4 = Xg[f];
        __nv_bfloat162 lo, hi;
        lo.x = __float2bfloat16(x4.x); lo.y = __float2bfloat16(x4.y);
        hi.x = __float2bfloat16(x4.z); hi.y = __float2bfloat16(x4.w);
        uint2 u2;
        u2.x = *reinterpret_cast<uint32_t*>(&lo);
        u2.y = *reinterpret_cast<uint32_t*>(&hi);
        *reinterpret_cast<uint2*>(smem + SM_X + sw128(aByte(r, k))) = u2;
    }
    __syncthreads();   // the ONLY barrier before the epilogue

    // ---- per-lane ldsm address constants (swizzle folded: disjoint bits) ----
    uint32_t koffA[4];
#pragma unroll
    for (int ks = 0; ks < 4; ks++)
        koffA[ks] = ((uint32_t)((lane >> 4) << 4) | (ks << 5)) ^ ((lane & 7) << 4);
    uint32_t aRowB[2];
#pragma unroll
    for (int mf = 0; mf < 2; mf++)
        aRowB[mf] = sb + SM_X +
            (uint32_t)(((wm * 4 + mf * 2 + ((lane >> 3) & 1)) << 10) | ((lane & 7) << 7));

    float acc[2][8][4];
    const float bias0 = bg[0];
    const int g = wn;

    // init accumulators with w1 (folds linear term in)
#pragma unroll
    for (int nf8 = 0; nf8 < 8; nf8++) {
        int c = g * 64 + nf8 * 8 + (lane & 3) * 2;
        float w0 = __ldg(&w1g[c]), w1v = __ldg(&w1g[c + 1]);
#pragma unroll
        for (int mf = 0; mf < 2; mf++) {
            acc[mf][nf8][0] = w0;  acc[mf][nf8][1] = w1v;
            acc[mf][nf8][2] = w0;  acc[mf][nf8][3] = w1v;
        }
    }

#pragma unroll 2
    for (int u = 0; u < 8; u++) {
        const uint4* gw = reinterpret_cast<const uint4*>(
            g_Gt + (((uint32_t)((u << 3) | g)) << 13) + ((uint32_t)lane << 4));
#pragma unroll
        for (int ks = 0; ks < 4; ks++) {
            uint4 bq[4];
#pragma unroll
            for (int p = 0; p < 4; p++)
                bq[p] = __ldg(gw + ((ks * 4 + p) << 5));
            uint32_t a[2][4];
#pragma unroll
            for (int mf = 0; mf < 2; mf++)
                ldsm4(a[mf], aRowB[mf] + ((uint32_t)u << 13) + koffA[ks]);
#pragma unroll
            for (int mf = 0; mf < 2; mf++) {
#pragma unroll
                for (int p = 0; p < 4; p++) {
                    mma16816(acc[mf][2 * p],     a[mf], bq[p].x, bq[p].y);
                    mma16816(acc[mf][2 * p + 1], a[mf], bq[p].z, bq[p].w);
                }
            }
        }
    }

    // ---- epilogue: sum += acc . x  (w1 already in) ----
#pragma unroll
    for (int mf = 0; mf < 2; mf++) {
        int r0 = wm * 32 + mf * 16 + (lane >> 2);
        int r1 = r0 + 8;
        float pA = 0.f, pB = 0.f;
#pragma unroll
        for (int nf8 = 0; nf8 < 8; nf8++) {
            int c = g * 64 + nf8 * 8 + (lane & 3) * 2;
            uint32_t xa = *reinterpret_cast<uint32_t*>(smem + SM_X + sw128(aByte(r0, c)));
            uint32_t xb = *reinterpret_cast<uint32_t*>(smem + SM_X + sw128(aByte(r1, c)));
            float x0 = __uint_as_float(xa << 16);
            float x1 = __uint_as_float(xa & 0xffff0000u);
            float y0 = __uint_as_float(xb << 16);
            float y1 = __uint_as_float(xb & 0xffff0000u);
            pA = fmaf(acc[mf][nf8][0], x0, pA);
            pA = fmaf(acc[mf][nf8][1], x1, pA);
            pB = fmaf(acc[mf][nf8][2], y0, pB);
            pB = fmaf(acc[mf][nf8][3], y1, pB);
        }
        pA += __shfl_xor_sync(0xffffffffu, pA, 1);
        pA += __shfl_xor_sync(0xffffffffu, pA, 2);
        pB += __shfl_xor_sync(0xffffffffu, pB, 1);
        pB += __shfl_xor_sync(0xffffffffu, pB, 2);
        if ((lane & 3) == 0) {
            atomicAdd(&accs[r0], pA);
            atomicAdd(&accs[r1], pB);
        }
    }

    __syncthreads();
    if (tid < MT) {
        float logit = accs[tid] + bias0;
        out[blockIdx.x * MT + tid] = 1.f / (1.f + expf(-logit));
    }
}

// ---------------------------------------------------------------------------
// kernel_launch
//   inputs: X [B,512] f32, w1 [512,1] f32, b [1] f32,
//           v [512,30,40] f32, feature2field [512] i32 ; output [B] f32
// ---------------------------------------------------------------------------
extern "C" void kernel_launch(void* const* d_in, const int* in_sizes, int n_in,
                              void* d_out, int out_size) {
    const float* X   = (const float*)d_in[0];
    const float* w1  = (const float*)d_in[1];
    const float* b   = (const float*)d_in[2];
    const float* v   = (const float*)d_in[3];
    const int*   f2f = (const int*)d_in[4];
    float* out = (float*)d_out;
    (void)n_in; (void)out_size;

    int Brows = in_sizes[0] / NF;

    static bool attr_set = false;
    if (!attr_set) {
        cudaFuncSetAttribute(ffm_hmma_kernel,
                             cudaFuncAttributeMaxDynamicSharedMemorySize, SM_TOT);
        attr_set = true;
    }

    build_G_kernel<<<NF, NF>>>(v, f2f);
    ffm_hmma_kernel<<<Brows / MT, NTHREADS, SM_TOT>>>(X, w1, b, out);
}

// round 15
// speedup vs baseline: 4.5904x; 4.5904x over previous
#include <cuda_runtime.h>
#include <cuda_bf16.h>
#include <cstdint>
#include <math.h>

#define NF 512
#define NFIELD 30
#define KDIM 40
#define MT 64           // rows per CTA
#define NTHREADS 256

// ---- smem layout (bytes) ----
#define SM_X      0
#define SM_X_BYTES (MT * NF * 2)            // 65536
#define SM_ACC    (SM_X + SM_X_BYTES)
#define SM_TOT    (SM_ACC + MT * 4)         // 65792

// G in mma-fragment order:
//   element (n, k):  u=k>>6, g=n>>6, ks=(k>>4)&3, p=(n>>4)&3, h=(n>>3)&1,
//                    kk=k&15, l=((n&7)<<2)|((kk&7)>>1), w=kk>>3, q=h*2+w
//   byte = ((u*8+g)<<13) + ((ks*4+p)<<9) + (l<<4) + (q<<2) + ((kk&1)<<1)
__device__ __align__(128) unsigned char g_Gt[NF * NF * 2];

// ---------------- helpers ----------------
__device__ __forceinline__ uint32_t smem_u32(const void* p) {
    uint32_t a;
    asm("{ .reg .u64 t; cvta.to.shared.u64 t, %1; cvt.u32.u64 %0, t; }" : "=r"(a) : "l"(p));
    return a;
}
__device__ __forceinline__ uint32_t sw128(uint32_t b) { return b ^ ((b >> 3) & 0x70); }
// X tile: blocked atoms (8 rows x 64 bf16 = 1024B); 8 atoms per 64-col group
__device__ __forceinline__ uint32_t aByte(int r, int k) {
    return (uint32_t)((((r >> 3) + (k >> 6) * 8) << 10) + ((r & 7) << 7) + ((k & 63) << 1));
}
__device__ __forceinline__ void ldsm4(uint32_t* r, uint32_t addr) {
    asm volatile("ldmatrix.sync.aligned.m8n8.x4.shared.b16 {%0,%1,%2,%3}, [%4];"
                 : "=r"(r[0]), "=r"(r[1]), "=r"(r[2]), "=r"(r[3]) : "r"(addr));
}
__device__ __forceinline__ void mma16816(float* c, const uint32_t* a, uint32_t b0, uint32_t b1) {
    asm volatile(
        "mma.sync.aligned.m16n8k16.row.col.f32.bf16.bf16.f32 "
        "{%0,%1,%2,%3}, {%4,%5,%6,%7}, {%8,%9}, {%0,%1,%2,%3};"
        : "+f"(c[0]), "+f"(c[1]), "+f"(c[2]), "+f"(c[3])
        : "r"(a[0]), "r"(a[1]), "r"(a[2]), "r"(a[3]), "r"(b0), "r"(b1));
}

// ---------------------------------------------------------------------------
// Kernel 1: G symmetric; write BOTH mirrors directly into fragment order.
// v[j,:,:] cached in smem (shared second factor for the whole CTA).
// ---------------------------------------------------------------------------
__device__ __forceinline__ void storeGt(int n, int k, __nv_bfloat16 h) {
    int u = k >> 6, g = n >> 6, ks = (k >> 4) & 3, p = (n >> 4) & 3;
    int hh = (n >> 3) & 1, kk = k & 15;
    int l = ((n & 7) << 2) | ((kk & 7) >> 1);
    int q = hh * 2 + (kk >> 3);
    uint32_t byte = ((uint32_t)((u << 3) | g) << 13) + ((uint32_t)((ks << 2) | p) << 9)
                  + ((uint32_t)l << 4) + ((uint32_t)q << 2) + ((uint32_t)(kk & 1) << 1);
    *reinterpret_cast<__nv_bfloat16*>(g_Gt + byte) = h;
}

__global__ void build_G_kernel(const float* __restrict__ v, const int* __restrict__ f2f) {
    __shared__ float vj[NFIELD * KDIM];
    int j = blockIdx.x;
    int i = threadIdx.x;
    // cache v[j, :, :] (1200 floats)
    for (int t = i; t < NFIELD * KDIM; t += NF)
        vj[t] = v[(size_t)j * NFIELD * KDIM + t];
    __syncthreads();
    if (i < j) return;
    int fj = __ldg(&f2f[j]);
    int fi = __ldg(&f2f[i]);
    const float4* a  = reinterpret_cast<const float4*>(v + ((size_t)i * NFIELD + fj) * KDIM);
    const float4* bp = reinterpret_cast<const float4*>(vj + fi * KDIM);
    float s = 0.f;
#pragma unroll
    for (int t = 0; t < KDIM / 4; t++) {
        float4 av = a[t], bv = bp[t];
        s = fmaf(av.x, bv.x, s);
        s = fmaf(av.y, bv.y, s);
        s = fmaf(av.z, bv.z, s);
        s = fmaf(av.w, bv.w, s);
    }
    s *= 0.5f;
    if (i == j) s = 0.f;
    __nv_bfloat16 h = __float2bfloat16(s);
    storeGt(j, i, h);   // B[n=j][k=i]
    storeGt(i, j, h);   // B[n=i][k=j]
}

// ---------------------------------------------------------------------------
// Kernel 2: HMMA quadratic form, barrier-free mainloop, 2 CTAs/SM.
//   MT=64, 8 warps: wm = wid&1 (2 x 32 rows), wn = wid>>1 (4 n-blocks of 64);
//   2 jt sweeps (g = jt*4+wn). Per-warp economy identical to R11 (m32 x n64,
//   2 ldsm + 4 LDG.128 + 8 mma per ks). Two independent barrier domains per
//   SM: CTA B's prologue/epilogue overlap CTA A's mainloop.
// ---------------------------------------------------------------------------
__global__ __launch_bounds__(NTHREADS, 2)
void ffm_hmma_kernel(const float* __restrict__ X, const float* __restrict__ w1g,
                     const float* __restrict__ bg, float* __restrict__ out) {
    extern __shared__ __align__(1024) char smem[];
    const int tid  = threadIdx.x;
    const int lane = tid & 31;
    const int wid  = tid >> 5;
    const int wm   = wid & 1;    // 2 x 32 rows
    const int wn   = wid >> 1;   // 4 x 64 cols

    uint32_t sb = smem_u32(smem);
    float* accs = reinterpret_cast<float*>(smem + SM_ACC);
    if (tid < MT) accs[tid] = 0.f;

    // ---- X prologue: 64 x 512 f32 -> bf16, swizzled blocked atoms ----
    const float4* Xg = reinterpret_cast<const float4*>(X + (size_t)blockIdx.x * MT * NF);
#pragma unroll 4
    for (int it = 0; it < 32; it++) {
        int f = tid + it * NTHREADS;
        int r = f >> 7;             // 128 float4 per row
        int k = (f & 127) * 4;
        float4 x4 = Xg[f];
        __nv_bfloat162 lo, hi;
        lo.x = __float2bfloat16(x4.x); lo.y = __float2bfloat16(x4.y);
        hi.x = __float2bfloat16(x4.z); hi.y = __float2bfloat16(x4.w);
        uint2 u2;
        u2.x = *reinterpret_cast<uint32_t*>(&lo);
        u2.y = *reinterpret_cast<uint32_t*>(&hi);
        *reinterpret_cast<uint2*>(smem + SM_X + sw128(aByte(r, k))) = u2;
    }
    __syncthreads();   // the ONLY barrier before the epilogue

    // ---- per-lane ldsm address constants (swizzle folded: disjoint bits) ----
    uint32_t koffA[4];
#pragma unroll
    for (int ks = 0; ks < 4; ks++)
        koffA[ks] = ((uint32_t)((lane >> 4) << 4) | (ks << 5)) ^ ((lane & 7) << 4);
    uint32_t aRowB[2];
#pragma unroll
    for (int mf = 0; mf < 2; mf++)
        aRowB[mf] = sb + SM_X +
            (uint32_t)(((wm * 4 + mf * 2 + ((lane >> 3) & 1)) << 10) | ((lane & 7) << 7));

    float acc[2][8][4];
    const float bias0 = bg[0];

#pragma unroll 1
    for (int jt = 0; jt < 2; jt++) {
        const int g = jt * 4 + wn;

        // init accumulators with w1 (folds linear term in)
#pragma unroll
        for (int nf8 = 0; nf8 < 8; nf8++) {
            int c = g * 64 + nf8 * 8 + (lane & 3) * 2;
            float w0 = __ldg(&w1g[c]), w1v = __ldg(&w1g[c + 1]);
#pragma unroll
            for (int mf = 0; mf < 2; mf++) {
                acc[mf][nf8][0] = w0;  acc[mf][nf8][1] = w1v;
                acc[mf][nf8][2] = w0;  acc[mf][nf8][3] = w1v;
            }
        }

#pragma unroll 2
        for (int u = 0; u < 8; u++) {
            const uint4* gw = reinterpret_cast<const uint4*>(
                g_Gt + (((uint32_t)((u << 3) | g)) << 13) + ((uint32_t)lane << 4));
#pragma unroll
            for (int ks = 0; ks < 4; ks++) {
                uint4 bq[4];
#pragma unroll
                for (int p = 0; p < 4; p++)
                    bq[p] = __ldg(gw + ((ks * 4 + p) << 5));
                uint32_t a[2][4];
#pragma unroll
                for (int mf = 0; mf < 2; mf++)
                    ldsm4(a[mf], aRowB[mf] + ((uint32_t)u << 13) + koffA[ks]);
#pragma unroll
                for (int mf = 0; mf < 2; mf++) {
#pragma unroll
                    for (int p = 0; p < 4; p++) {
                        mma16816(acc[mf][2 * p],     a[mf], bq[p].x, bq[p].y);
                        mma16816(acc[mf][2 * p + 1], a[mf], bq[p].z, bq[p].w);
                    }
                }
            }
        }

        // ---- epilogue for this sweep: sum += acc . x  (w1 already in) ----
#pragma unroll
        for (int mf = 0; mf < 2; mf++) {
            int r0 = wm * 32 + mf * 16 + (lane >> 2);
            int r1 = r0 + 8;
            float pA = 0.f, pB = 0.f;
#pragma unroll
            for (int nf8 = 0; nf8 < 8; nf8++) {
                int c = g * 64 + nf8 * 8 + (lane & 3) * 2;
                uint32_t xa = *reinterpret_cast<uint32_t*>(smem + SM_X + sw128(aByte(r0, c)));
                uint32_t xb = *reinterpret_cast<uint32_t*>(smem + SM_X + sw128(aByte(r1, c)));
                float x0 = __uint_as_float(xa << 16);
                float x1 = __uint_as_float(xa & 0xffff0000u);
                float y0 = __uint_as_float(xb << 16);
                float y1 = __uint_as_float(xb & 0xffff0000u);
                pA = fmaf(acc[mf][nf8][0], x0, pA);
                pA = fmaf(acc[mf][nf8][1], x1, pA);
                pB = fmaf(acc[mf][nf8][2], y0, pB);
                pB = fmaf(acc[mf][nf8][3], y1, pB);
            }
            pA += __shfl_xor_sync(0xffffffffu, pA, 1);
            pA += __shfl_xor_sync(0xffffffffu, pA, 2);
            pB += __shfl_xor_sync(0xffffffffu, pB, 1);
            pB += __shfl_xor_sync(0xffffffffu, pB, 2);
            if ((lane & 3) == 0) {
                atomicAdd(&accs[r0], pA);
                atomicAdd(&accs[r1], pB);
            }
        }
    }

    __syncthreads();
    if (tid < MT) {
        float logit = accs[tid] + bias0;
        out[blockIdx.x * MT + tid] = 1.f / (1.f + expf(-logit));
    }
}

// ---------------------------------------------------------------------------
// kernel_launch
//   inputs: X [B,512] f32, w1 [512,1] f32, b [1] f32,
//           v [512,30,40] f32, feature2field [512] i32 ; output [B] f32
// ---------------------------------------------------------------------------
extern "C" void kernel_launch(void* const* d_in, const int* in_sizes, int n_in,
                              void* d_out, int out_size) {
    const float* X   = (const float*)d_in[0];
    const float* w1  = (const float*)d_in[1];
    const float* b   = (const float*)d_in[2];
    const float* v   = (const float*)d_in[3];
    const int*   f2f = (const int*)d_in[4];
    float* out = (float*)d_out;
    (void)n_in; (void)out_size;

    int Brows = in_sizes[0] / NF;

    static bool attr_set = false;
    if (!attr_set) {
        cudaFuncSetAttribute(ffm_hmma_kernel,
                             cudaFuncAttributeMaxDynamicSharedMemorySize, SM_TOT);
        attr_set = true;
    }

    build_G_kernel<<<NF, NF>>>(v, f2f);
    ffm_hmma_kernel<<<Brows / MT, NTHREADS, SM_TOT>>>(X, w1, b, out);
}

// round 16
// speedup vs baseline: 5.9765x; 1.3020x over previous
#include <cuda_runtime.h>
#include <cuda_bf16.h>
#include <cstdint>
#include <math.h>

#define NF 512
#define NFIELD 30
#define KDIM 40
#define MT 128          // rows per CTA
#define NTHREADS 512

// ---- smem layout (bytes) ----
#define SM_X      0
#define SM_X_BYTES (MT * NF * 2)            // 131072
#define SM_ACC    (SM_X + SM_X_BYTES)
#define SM_TOT    (SM_ACC + MT * 4)         // 131584

// G2 in mma-fragment order, TRIANGULAR blocks only (k-block u <= n-block g),
// off-diagonal blocks pre-doubled (exact in bf16):
//   element (n, k):  u=k>>6, g=n>>6, ks=(k>>4)&3, p=(n>>4)&3, h=(n>>3)&1,
//                    kk=k&15, l=((n&7)<<2)|((kk&7)>>1), w=kk>>3, q=h*2+w
//   byte = ((u*8+g)<<13) + ((ks*4+p)<<9) + (l<<4) + (q<<2) + ((kk&1)<<1)
__device__ __align__(128) unsigned char g_Gt[NF * NF * 2];

// ---------------- helpers ----------------
__device__ __forceinline__ uint32_t smem_u32(const void* p) {
    uint32_t a;
    asm("{ .reg .u64 t; cvta.to.shared.u64 t, %1; cvt.u32.u64 %0, t; }" : "=r"(a) : "l"(p));
    return a;
}
__device__ __forceinline__ uint32_t sw128(uint32_t b) { return b ^ ((b >> 3) & 0x70); }
// X tile: blocked atoms (8 rows x 64 bf16 = 1024B); atom = (r>>3) + (k>>6)*16
__device__ __forceinline__ uint32_t aByte(int r, int k) {
    return (uint32_t)((((r >> 3) + (k >> 6) * 16) << 10) + ((r & 7) << 7) + ((k & 63) << 1));
}
__device__ __forceinline__ void ldsm4(uint32_t* r, uint32_t addr) {
    asm volatile("ldmatrix.sync.aligned.m8n8.x4.shared.b16 {%0,%1,%2,%3}, [%4];"
                 : "=r"(r[0]), "=r"(r[1]), "=r"(r[2]), "=r"(r[3]) : "r"(addr));
}
__device__ __forceinline__ void mma16816(float* c, const uint32_t* a, uint32_t b0, uint32_t b1) {
    asm volatile(
        "mma.sync.aligned.m16n8k16.row.col.f32.bf16.bf16.f32 "
        "{%0,%1,%2,%3}, {%4,%5,%6,%7}, {%8,%9}, {%0,%1,%2,%3};"
        : "+f"(c[0]), "+f"(c[1]), "+f"(c[2]), "+f"(c[3])
        : "r"(a[0]), "r"(a[1]), "r"(a[2]), "r"(a[3]), "r"(b0), "r"(b1));
}

// ---------------------------------------------------------------------------
// Kernel 1: triangular-block G2 in fragment order.
//   For feature pair (i >= j), h = 0.5 * C[i][j]:
//     same 64-block (i>>6 == j>>6): store h at (n=i,k=j) AND (n=j,k=i)
//     different blocks: store 2h at (n=i,k=j) only  (n-block > k-block)
// ---------------------------------------------------------------------------
__device__ __forceinline__ void storeGt(int n, int k, __nv_bfloat16 h) {
    int u = k >> 6, g = n >> 6, ks = (k >> 4) & 3, p = (n >> 4) & 3;
    int hh = (n >> 3) & 1, kk = k & 15;
    int l = ((n & 7) << 2) | ((kk & 7) >> 1);
    int q = hh * 2 + (kk >> 3);
    uint32_t byte = ((uint32_t)((u << 3) | g) << 13) + ((uint32_t)((ks << 2) | p) << 9)
                  + ((uint32_t)l << 4) + ((uint32_t)q << 2) + ((uint32_t)(kk & 1) << 1);
    *reinterpret_cast<__nv_bfloat16*>(g_Gt + byte) = h;
}

__global__ void build_G_kernel(const float* __restrict__ v, const int* __restrict__ f2f) {
    __shared__ float vj[NFIELD * KDIM];
    int j = blockIdx.x;
    int i = threadIdx.x;
    for (int t = i; t < NFIELD * KDIM; t += NF)
        vj[t] = v[(size_t)j * NFIELD * KDIM + t];
    __syncthreads();
    if (i < j) return;
    int fj = __ldg(&f2f[j]);
    int fi = __ldg(&f2f[i]);
    const float4* a  = reinterpret_cast<const float4*>(v + ((size_t)i * NFIELD + fj) * KDIM);
    const float4* bp = reinterpret_cast<const float4*>(vj + fi * KDIM);
    float s = 0.f;
#pragma unroll
    for (int t = 0; t < KDIM / 4; t++) {
        float4 av = a[t], bv = bp[t];
        s = fmaf(av.x, bv.x, s);
        s = fmaf(av.y, bv.y, s);
        s = fmaf(av.z, bv.z, s);
        s = fmaf(av.w, bv.w, s);
    }
    s *= 0.5f;
    if (i == j) s = 0.f;
    if ((i >> 6) == (j >> 6)) {
        __nv_bfloat16 h = __float2bfloat16(s);
        storeGt(i, j, h);
        storeGt(j, i, h);
    } else {
        storeGt(i, j, __float2bfloat16(s * 2.f));   // doubled off-diag block
    }
}

// ---------------------------------------------------------------------------
// Kernel 2: HMMA quadratic form, barrier-free mainloop, TRIANGULAR blocks.
//   16 warps: wm = wid&3 (4 x 32 rows), wn = wid>>2.
//   Warp wn handles n-blocks {wn, 7-wn}; block g needs k-chunks u = 0..g.
//   Total 9 chunks per warp (vs 16 full) — perfectly balanced.
// ---------------------------------------------------------------------------
__global__ __launch_bounds__(NTHREADS, 1)
void ffm_hmma_kernel(const float* __restrict__ X, const float* __restrict__ w1g,
                     const float* __restrict__ bg, float* __restrict__ out) {
    extern __shared__ __align__(1024) char smem[];
    const int tid  = threadIdx.x;
    const int lane = tid & 31;
    const int wid  = tid >> 5;
    const int wm   = wid & 3;
    const int wn   = wid >> 2;

    uint32_t sb = smem_u32(smem);
    float* accs = reinterpret_cast<float*>(smem + SM_ACC);
    if (tid < MT) accs[tid] = 0.f;

    // ---- X prologue: 128 x 512 f32 -> bf16, swizzled blocked atoms ----
    const float4* Xg = reinterpret_cast<const float4*>(X + (size_t)blockIdx.x * MT * NF);
#pragma unroll 4
    for (int it = 0; it < 32; it++) {
        int f = tid + it * NTHREADS;
        int r = f >> 7;             // 128 float4 per row
        int k = (f & 127) * 4;
        float4 x4 = Xg[f];
        __nv_bfloat162 lo, hi;
        lo.x = __float2bfloat16(x4.x); lo.y = __float2bfloat16(x4.y);
        hi.x = __float2bfloat16(x4.z); hi.y = __float2bfloat16(x4.w);
        uint2 u2;
        u2.x = *reinterpret_cast<uint32_t*>(&lo);
        u2.y = *reinterpret_cast<uint32_t*>(&hi);
        *reinterpret_cast<uint2*>(smem + SM_X + sw128(aByte(r, k))) = u2;
    }
    __syncthreads();   // the ONLY barrier before the epilogue

    // ---- per-lane ldsm address constants (swizzle folded: disjoint bits) ----
    uint32_t koffA[4];
#pragma unroll
    for (int ks = 0; ks < 4; ks++)
        koffA[ks] = ((uint32_t)((lane >> 4) << 4) | (ks << 5)) ^ ((lane & 7) << 4);
    uint32_t aRowB[2];
#pragma unroll
    for (int mf = 0; mf < 2; mf++)
        aRowB[mf] = sb + SM_X +
            (uint32_t)(((wm * 4 + mf * 2 + ((lane >> 3) & 1)) << 10) | ((lane & 7) << 7));

    float acc[2][8][4];
    const float bias0 = bg[0];

#pragma unroll 1
    for (int jt = 0; jt < 2; jt++) {
        const int g = jt ? (7 - wn) : wn;   // balanced pair {wn, 7-wn}

        // init accumulators with w1 (folds linear term in)
#pragma unroll
        for (int nf8 = 0; nf8 < 8; nf8++) {
            int c = g * 64 + nf8 * 8 + (lane & 3) * 2;
            float w0 = __ldg(&w1g[c]), w1v = __ldg(&w1g[c + 1]);
#pragma unroll
            for (int mf = 0; mf < 2; mf++) {
                acc[mf][nf8][0] = w0;  acc[mf][nf8][1] = w1v;
                acc[mf][nf8][2] = w0;  acc[mf][nf8][3] = w1v;
            }
        }

        // triangular k-chunk loop: u = 0..g
#pragma unroll 2
        for (int u = 0; u <= g; u++) {
            const uint4* gw = reinterpret_cast<const uint4*>(
                g_Gt + (((uint32_t)((u << 3) | g)) << 13) + ((uint32_t)lane << 4));
#pragma unroll
            for (int ks = 0; ks < 4; ks++) {
                uint4 bq[4];
#pragma unroll
                for (int p = 0; p < 4; p++)
                    bq[p] = __ldg(gw + ((ks * 4 + p) << 5));
                uint32_t a[2][4];
#pragma unroll
                for (int mf = 0; mf < 2; mf++)
                    ldsm4(a[mf], aRowB[mf] + ((uint32_t)u << 14) + koffA[ks]);
#pragma unroll
                for (int mf = 0; mf < 2; mf++) {
#pragma unroll
                    for (int p = 0; p < 4; p++) {
                        mma16816(acc[mf][2 * p],     a[mf], bq[p].x, bq[p].y);
                        mma16816(acc[mf][2 * p + 1], a[mf], bq[p].z, bq[p].w);
                    }
                }
            }
        }

        // ---- epilogue for this n-block: sum += acc . x  (w1 already in) ----
#pragma unroll
        for (int mf = 0; mf < 2; mf++) {
            int r0 = wm * 32 + mf * 16 + (lane >> 2);
            int r1 = r0 + 8;
            float pA = 0.f, pB = 0.f;
#pragma unroll
            for (int nf8 = 0; nf8 < 8; nf8++) {
                int c = g * 64 + nf8 * 8 + (lane & 3) * 2;
                uint32_t xa = *reinterpret_cast<uint32_t*>(smem + SM_X + sw128(aByte(r0, c)));
                uint32_t xb = *reinterpret_cast<uint32_t*>(smem + SM_X + sw128(aByte(r1, c)));
                float x0 = __uint_as_float(xa << 16);
                float x1 = __uint_as_float(xa & 0xffff0000u);
                float y0 = __uint_as_float(xb << 16);
                float y1 = __uint_as_float(xb & 0xffff0000u);
                pA = fmaf(acc[mf][nf8][0], x0, pA);
                pA = fmaf(acc[mf][nf8][1], x1, pA);
                pB = fmaf(acc[mf][nf8][2], y0, pB);
                pB = fmaf(acc[mf][nf8][3], y1, pB);
            }
            pA += __shfl_xor_sync(0xffffffffu, pA, 1);
            pA += __shfl_xor_sync(0xffffffffu, pA, 2);
            pB += __shfl_xor_sync(0xffffffffu, pB, 1);
            pB += __shfl_xor_sync(0xffffffffu, pB, 2);
            if ((lane & 3) == 0) {
                atomicAdd(&accs[r0], pA);
                atomicAdd(&accs[r1], pB);
            }
        }
    }

    __syncthreads();
    if (tid < MT) {
        float logit = accs[tid] + bias0;
        out[blockIdx.x * MT + tid] = 1.f / (1.f + expf(-logit));
    }
}

// ---------------------------------------------------------------------------
// kernel_launch
//   inputs: X [B,512] f32, w1 [512,1] f32, b [1] f32,
//           v [512,30,40] f32, feature2field [512] i32 ; output [B] f32
// ---------------------------------------------------------------------------
extern "C" void kernel_launch(void* const* d_in, const int* in_sizes, int n_in,
                              void* d_out, int out_size) {
    const float* X   = (const float*)d_in[0];
    const float* w1  = (const float*)d_in[1];
    const float* b   = (const float*)d_in[2];
    const float* v   = (const float*)d_in[3];
    const int*   f2f = (const int*)d_in[4];
    float* out = (float*)d_out;
    (void)n_in; (void)out_size;

    int Brows = in_sizes[0] / NF;

    static bool attr_set = false;
    if (!attr_set) {
        cudaFuncSetAttribute(ffm_hmma_kernel,
                             cudaFuncAttributeMaxDynamicSharedMemorySize, SM_TOT);
        attr_set = true;
    }

    build_G_kernel<<<NF, NF>>>(v, f2f);
    ffm_hmma_kernel<<<Brows / MT, NTHREADS, SM_TOT>>>(X, w1, b, out);
}

// round 17
// speedup vs baseline: 6.1758x; 1.0334x over previous
#include <cuda_runtime.h>
#include <cuda_bf16.h>
#include <cstdint>
#include <math.h>

#define NF 512
#define NFIELD 30
#define KDIM 40
#define MT 128          // rows per CTA
#define NTHREADS 512

// ---- smem layout (bytes) ----
#define SM_X      0
#define SM_X_BYTES (MT * NF * 2)            // 131072
#define SM_ACC    (SM_X + SM_X_BYTES)
#define SM_TOT    (SM_ACC + MT * 4)         // 131584

// G2 in mma-fragment order, TRIANGULAR blocks only (k-block u <= n-block g),
// off-diagonal blocks pre-doubled (exact in bf16):
//   element (n, k):  u=k>>6, g=n>>6, ks=(k>>4)&3, p=(n>>4)&3, h=(n>>3)&1,
//                    kk=k&15, l=((n&7)<<2)|((kk&7)>>1), w=kk>>3, q=h*2+w
//   byte = ((u*8+g)<<13) + ((ks*4+p)<<9) + (l<<4) + (q<<2) + ((kk&1)<<1)
__device__ __align__(128) unsigned char g_Gt[NF * NF * 2];

// ---------------- helpers ----------------
__device__ __forceinline__ uint32_t smem_u32(const void* p) {
    uint32_t a;
    asm("{ .reg .u64 t; cvta.to.shared.u64 t, %1; cvt.u32.u64 %0, t; }" : "=r"(a) : "l"(p));
    return a;
}
__device__ __forceinline__ uint32_t sw128(uint32_t b) { return b ^ ((b >> 3) & 0x70); }
// X tile: blocked atoms (8 rows x 64 bf16 = 1024B); atom = (r>>3) + (k>>6)*16
__device__ __forceinline__ uint32_t aByte(int r, int k) {
    return (uint32_t)((((r >> 3) + (k >> 6) * 16) << 10) + ((r & 7) << 7) + ((k & 63) << 1));
}
__device__ __forceinline__ void ldsm4(uint32_t* r, uint32_t addr) {
    asm volatile("ldmatrix.sync.aligned.m8n8.x4.shared.b16 {%0,%1,%2,%3}, [%4];"
                 : "=r"(r[0]), "=r"(r[1]), "=r"(r[2]), "=r"(r[3]) : "r"(addr));
}
__device__ __forceinline__ void mma16816(float* c, const uint32_t* a, uint32_t b0, uint32_t b1) {
    asm volatile(
        "mma.sync.aligned.m16n8k16.row.col.f32.bf16.bf16.f32 "
        "{%0,%1,%2,%3}, {%4,%5,%6,%7}, {%8,%9}, {%0,%1,%2,%3};"
        : "+f"(c[0]), "+f"(c[1]), "+f"(c[2]), "+f"(c[3])
        : "r"(a[0]), "r"(a[1]), "r"(a[2]), "r"(a[3]), "r"(b0), "r"(b1));
}

// ---------------------------------------------------------------------------
// Kernel 1: triangular-block G2 in fragment order.
// ---------------------------------------------------------------------------
__device__ __forceinline__ void storeGt(int n, int k, __nv_bfloat16 h) {
    int u = k >> 6, g = n >> 6, ks = (k >> 4) & 3, p = (n >> 4) & 3;
    int hh = (n >> 3) & 1, kk = k & 15;
    int l = ((n & 7) << 2) | ((kk & 7) >> 1);
    int q = hh * 2 + (kk >> 3);
    uint32_t byte = ((uint32_t)((u << 3) | g) << 13) + ((uint32_t)((ks << 2) | p) << 9)
                  + ((uint32_t)l << 4) + ((uint32_t)q << 2) + ((uint32_t)(kk & 1) << 1);
    *reinterpret_cast<__nv_bfloat16*>(g_Gt + byte) = h;
}

__global__ void build_G_kernel(const float* __restrict__ v, const int* __restrict__ f2f) {
    __shared__ float vj[NFIELD * KDIM];
    int j = blockIdx.x;
    int i = threadIdx.x;
    for (int t = i; t < NFIELD * KDIM; t += NF)
        vj[t] = v[(size_t)j * NFIELD * KDIM + t];
    __syncthreads();
    if (i < j) return;
    int fj = __ldg(&f2f[j]);
    int fi = __ldg(&f2f[i]);
    const float4* a  = reinterpret_cast<const float4*>(v + ((size_t)i * NFIELD + fj) * KDIM);
    const float4* bp = reinterpret_cast<const float4*>(vj + fi * KDIM);
    float s = 0.f;
#pragma unroll
    for (int t = 0; t < KDIM / 4; t++) {
        float4 av = a[t], bv = bp[t];
        s = fmaf(av.x, bv.x, s);
        s = fmaf(av.y, bv.y, s);
        s = fmaf(av.z, bv.z, s);
        s = fmaf(av.w, bv.w, s);
    }
    s *= 0.5f;
    if (i == j) s = 0.f;
    if ((i >> 6) == (j >> 6)) {
        __nv_bfloat16 h = __float2bfloat16(s);
        storeGt(i, j, h);
        storeGt(j, i, h);
    } else {
        storeGt(i, j, __float2bfloat16(s * 2.f));   // doubled off-diag block
    }
}

// ---------------------------------------------------------------------------
// Kernel 2: HMMA quadratic form, barrier-free, triangular, B double-buffered.
//   16 warps: wm = wid&3 (4 x 32 rows), wn = wid>>2; blocks {wn, 7-wn}.
//   Flattened (u,ks) step stream with one-step-ahead B prefetch (bqA/bqB).
// ---------------------------------------------------------------------------
__global__ __launch_bounds__(NTHREADS, 1)
void ffm_hmma_kernel(const float* __restrict__ X, const float* __restrict__ w1g,
                     const float* __restrict__ bg, float* __restrict__ out) {
    extern __shared__ __align__(1024) char smem[];
    const int tid  = threadIdx.x;
    const int lane = tid & 31;
    const int wid  = tid >> 5;
    const int wm   = wid & 3;
    const int wn   = wid >> 2;

    uint32_t sb = smem_u32(smem);
    float* accs = reinterpret_cast<float*>(smem + SM_ACC);
    if (tid < MT) accs[tid] = 0.f;

    // ---- X prologue: 128 x 512 f32 -> bf16, swizzled blocked atoms ----
    const float4* Xg = reinterpret_cast<const float4*>(X + (size_t)blockIdx.x * MT * NF);
#pragma unroll 4
    for (int it = 0; it < 32; it++) {
        int f = tid + it * NTHREADS;
        int r = f >> 7;             // 128 float4 per row
        int k = (f & 127) * 4;
        float4 x4 = Xg[f];
        __nv_bfloat162 lo, hi;
        lo.x = __float2bfloat16(x4.x); lo.y = __float2bfloat16(x4.y);
        hi.x = __float2bfloat16(x4.z); hi.y = __float2bfloat16(x4.w);
        uint2 u2;
        u2.x = *reinterpret_cast<uint32_t*>(&lo);
        u2.y = *reinterpret_cast<uint32_t*>(&hi);
        *reinterpret_cast<uint2*>(smem + SM_X + sw128(aByte(r, k))) = u2;
    }
    __syncthreads();   // the ONLY barrier before the epilogue

    // ---- per-lane ldsm address constants (swizzle folded: disjoint bits) ----
    uint32_t koffA[4];
#pragma unroll
    for (int ks = 0; ks < 4; ks++)
        koffA[ks] = ((uint32_t)((lane >> 4) << 4) | (ks << 5)) ^ ((lane & 7) << 4);
    uint32_t aRowB[2];
#pragma unroll
    for (int mf = 0; mf < 2; mf++)
        aRowB[mf] = sb + SM_X +
            (uint32_t)(((wm * 4 + mf * 2 + ((lane >> 3) & 1)) << 10) | ((lane & 7) << 7));

    float acc[2][8][4];
    const float bias0 = bg[0];

#pragma unroll 1
    for (int jt = 0; jt < 2; jt++) {
        const int g = jt ? (7 - wn) : wn;   // balanced pair {wn, 7-wn}

        // init accumulators with w1 (folds linear term in)
#pragma unroll
        for (int nf8 = 0; nf8 < 8; nf8++) {
            int c = g * 64 + nf8 * 8 + (lane & 3) * 2;
            float w0 = __ldg(&w1g[c]), w1v = __ldg(&w1g[c + 1]);
#pragma unroll
            for (int mf = 0; mf < 2; mf++) {
                acc[mf][nf8][0] = w0;  acc[mf][nf8][1] = w1v;
                acc[mf][nf8][2] = w0;  acc[mf][nf8][3] = w1v;
            }
        }

        // flattened step stream: step s -> u = s>>2, ks = s&3 ; steps = 4*(g+1)
        const unsigned char* gbase = g_Gt + ((uint32_t)g << 13) + ((uint32_t)lane << 4);
        const int steps = (g + 1) * 4;

        uint4 bqA[4], bqB[4];
        // off(s) = ((s>>2)<<16) + ((s&3)<<11) ; p stride = 512B
#define LOADB(bq, s_) do {                                                        \
            const uint4* gw_ = reinterpret_cast<const uint4*>(                    \
                gbase + (((uint32_t)((s_) >> 2)) << 16) + (((uint32_t)((s_) & 3)) << 11)); \
            (bq)[0] = __ldg(gw_);       (bq)[1] = __ldg(gw_ + 32);                \
            (bq)[2] = __ldg(gw_ + 64);  (bq)[3] = __ldg(gw_ + 96);                \
        } while (0)
#define DOSTEP(bq, s_) do {                                                       \
            uint32_t a_[2][4];                                                    \
            uint32_t au_ = (((uint32_t)((s_) >> 2)) << 14) + koffA[(s_) & 3];     \
            ldsm4(a_[0], aRowB[0] + au_);                                         \
            ldsm4(a_[1], aRowB[1] + au_);                                         \
            _Pragma("unroll")                                                     \
            for (int mf = 0; mf < 2; mf++) {                                      \
                _Pragma("unroll")                                                 \
                for (int p = 0; p < 4; p++) {                                     \
                    mma16816(acc[mf][2 * p],     a_[mf], (bq)[p].x, (bq)[p].y);   \
                    mma16816(acc[mf][2 * p + 1], a_[mf], (bq)[p].z, (bq)[p].w);   \
                }                                                                 \
            }                                                                     \
        } while (0)

        LOADB(bqA, 0);
#pragma unroll 1
        for (int s = 0; s < steps; s += 2) {
            LOADB(bqB, s + 1);          // prefetch step s+1 (steps is even)
            DOSTEP(bqA, s);
            if (s + 2 < steps) LOADB(bqA, s + 2);
            DOSTEP(bqB, s + 1);
        }
#undef LOADB
#undef DOSTEP

        // ---- epilogue for this n-block: sum += acc . x  (w1 already in) ----
#pragma unroll
        for (int mf = 0; mf < 2; mf++) {
            int r0 = wm * 32 + mf * 16 + (lane >> 2);
            int r1 = r0 + 8;
            float pA = 0.f, pB = 0.f;
#pragma unroll
            for (int nf8 = 0; nf8 < 8; nf8++) {
                int c = g * 64 + nf8 * 8 + (lane & 3) * 2;
                uint32_t xa = *reinterpret_cast<uint32_t*>(smem + SM_X + sw128(aByte(r0, c)));
                uint32_t xb = *reinterpret_cast<uint32_t*>(smem + SM_X + sw128(aByte(r1, c)));
                float x0 = __uint_as_float(xa << 16);
                float x1 = __uint_as_float(xa & 0xffff0000u);
                float y0 = __uint_as_float(xb << 16);
                float y1 = __uint_as_float(xb & 0xffff0000u);
                pA = fmaf(acc[mf][nf8][0], x0, pA);
                pA = fmaf(acc[mf][nf8][1], x1, pA);
                pB = fmaf(acc[mf][nf8][2], y0, pB);
                pB = fmaf(acc[mf][nf8][3], y1, pB);
            }
            pA += __shfl_xor_sync(0xffffffffu, pA, 1);
            pA += __shfl_xor_sync(0xffffffffu, pA, 2);
            pB += __shfl_xor_sync(0xffffffffu, pB, 1);
            pB += __shfl_xor_sync(0xffffffffu, pB, 2);
            if ((lane & 3) == 0) {
                atomicAdd(&accs[r0], pA);
                atomicAdd(&accs[r1], pB);
            }
        }
    }

    __syncthreads();
    if (tid < MT) {
        float logit = accs[tid] + bias0;
        out[blockIdx.x * MT + tid] = 1.f / (1.f + expf(-logit));
    }
}

// ---------------------------------------------------------------------------
// kernel_launch
//   inputs: X [B,512] f32, w1 [512,1] f32, b [1] f32,
//           v [512,30,40] f32, feature2field [512] i32 ; output [B] f32
// ---------------------------------------------------------------------------
extern "C" void kernel_launch(void* const* d_in, const int* in_sizes, int n_in,
                              void* d_out, int out_size) {
    const float* X   = (const float*)d_in[0];
    const float* w1  = (const float*)d_in[1];
    const float* b   = (const float*)d_in[2];
    const float* v   = (const float*)d_in[3];
    const int*   f2f = (const int*)d_in[4];
    float* out = (float*)d_out;
    (void)n_in; (void)out_size;

    int Brows = in_sizes[0] / NF;

    static bool attr_set = false;
    if (!attr_set) {
        cudaFuncSetAttribute(ffm_hmma_kernel,
                             cudaFuncAttributeMaxDynamicSharedMemorySize, SM_TOT);
        attr_set = true;
    }

    build_G_kernel<<<NF, NF>>>(v, f2f);
    ffm_hmma_kernel<<<Brows / MT, NTHREADS, SM_TOT>>>(X, w1, b, out);
}